// round 13
// baseline (speedup 1.0000x reference)
#include <cuda_runtime.h>
#include <cuda_bf16.h>
#include <cstdint>

// ---------------------------------------------------------------------------
// GCN 2-layer: h = relu(GCNConv(x,W1,b1)); z = GCNConv(h,W2,b2)
// out = [ segment_max(z,batch) (64x7) ; log_softmax(z) (Nx7) ]
// edge_index/batch are int32. No tcgen05 (compute_103 PTX target).
// GEMM1: cp.async 16B phase-aligned loader + packed fma.rn.f32x2.
// Aggregation: CSR gather (rank captured during count -> atomic-free scatter).
// ---------------------------------------------------------------------------

#define MAXN 100352
#define MAXE 3356672
#define NUM_GRAPHS 64
#define HID 16
#define NCLS 7
#define BM 256       // nodes per CTA in gemm1
#define BK 16        // k-chunk
#define XSW 20       // smem row stride (floats) in gemm1

// ---- scratch (device globals; no allocation allowed) ----------------------
__device__ int      g_cnt[MAXN];      // in-degree (no self-loop)
__device__ int      g_start[MAXN];    // CSR segment start
__device__ int      g_rank[MAXE];     // per-edge rank within its dst segment
__device__ int      g_ebuf[MAXE];     // src indices grouped by dst
__device__ int      g_total;
__device__ float    g_dinv[MAXN];
__device__ float4   g_h0[MAXN * 4];   // [N][16]  (x@W1) * dinv  (pre-scaled)
__device__ float4   g_a1[MAXN * 4];   // [N][16]  aggregated + b1
__device__ float4   g_h1[MAXN * 2];   // [N][8]   (relu(a1)@W2) * dinv (pre-scaled)
__device__ float4   g_z [MAXN * 2];   // [N][8]   aggregated z
__device__ unsigned g_gkey[NUM_GRAPHS * NCLS];

// ---- helpers --------------------------------------------------------------

__device__ __forceinline__ unsigned fkey(float f) {
    unsigned u = __float_as_uint(f);
    return (u & 0x80000000u) ? ~u : (u | 0x80000000u);
}
__device__ __forceinline__ float funkey(unsigned u) {
    return __uint_as_float((u & 0x80000000u) ? (u ^ 0x80000000u) : ~u);
}

__device__ __forceinline__ uint32_t smem_u32(const void* p) {
    return (uint32_t)__cvta_generic_to_shared(p);
}
__device__ __forceinline__ void cp16(uint32_t dst, const float* src) {
    asm volatile("cp.async.ca.shared.global [%0], [%1], 16;"
                 :: "r"(dst), "l"(src) : "memory");
}
__device__ __forceinline__ void cp4(uint32_t dst, const float* src) {
    asm volatile("cp.async.ca.shared.global [%0], [%1], 4;"
                 :: "r"(dst), "l"(src) : "memory");
}
__device__ __forceinline__ void cp4p(uint32_t dst, const float* src, bool inb) {
    int sz = inb ? 4 : 0;
    asm volatile("cp.async.ca.shared.global [%0], [%1], 4, %2;"
                 :: "r"(dst), "l"(src), "r"(sz) : "memory");
}
#define CP_COMMIT() asm volatile("cp.async.commit_group;" ::: "memory")

// packed fp32x2 (Blackwell FFMA2; bit-identical per-lane fp32)
__device__ __forceinline__ void fma2(unsigned long long& d,
                                     unsigned long long a, unsigned long long b) {
    asm("fma.rn.f32x2 %0, %1, %2, %3;" : "=l"(d) : "l"(a), "l"(b), "l"(d));
}
__device__ __forceinline__ unsigned long long bcast2(float v) {
    unsigned long long r;
    asm("mov.b64 %0, {%1, %1};" : "=l"(r) : "f"(v));
    return r;
}
__device__ __forceinline__ float2 unpack2(unsigned long long v) {
    float lo, hi;
    asm("mov.b64 {%0, %1}, %2;" : "=f"(lo), "=f"(hi) : "l"(v));
    return make_float2(lo, hi);
}

// ---- CSR construction -----------------------------------------------------

__global__ void zero_kernel(int N) {
    int i = blockIdx.x * blockDim.x + threadIdx.x;
    if (i < N) g_cnt[i] = 0;
    if (i < NUM_GRAPHS * NCLS) g_gkey[i] = 0u;
    if (i == 0) g_total = 0;
}

// count in-degree AND capture each edge's rank within its dst segment
__global__ void count_kernel(const int* __restrict__ ei, int E) {
    int e = blockIdx.x * blockDim.x + threadIdx.x;
    if (e >= E) return;
    g_rank[e] = atomicAdd(&g_cnt[ei[E + e]], 1);
}

// block-scan of counts -> per-node segment start + dinv
__global__ void scan_kernel(int N) {
    __shared__ int sdata[256];
    __shared__ int base;
    int tid = threadIdx.x;
    int n = blockIdx.x * 256 + tid;
    int c = (n < N) ? g_cnt[n] : 0;
    sdata[tid] = c;
    __syncthreads();
#pragma unroll
    for (int off = 1; off < 256; off <<= 1) {
        int v = (tid >= off) ? sdata[tid - off] : 0;
        __syncthreads();
        sdata[tid] += v;
        __syncthreads();
    }
    if (tid == 255) base = atomicAdd(&g_total, sdata[255]);
    __syncthreads();
    if (n < N) {
        g_start[n] = base + sdata[tid] - c;
        g_dinv[n]  = rsqrtf((float)(c + 1));   // +1 self-loop
    }
}

// atomic-free scatter using captured ranks
__global__ void scatter_kernel(const int* __restrict__ ei, int E) {
    int e = blockIdx.x * blockDim.x + threadIdx.x;
    if (e >= E) return;
    int s = ei[e];
    int d = ei[E + e];
    g_ebuf[g_start[d] + g_rank[e]] = s;
}

// ---- GEMM1: h0s[N,16] = (x@W1)*dinv; a1 = h0s*dinv + b1 (fused) -----------
// Fast-path loader: per row a 16B-aligned 20-float window [k0-ph, k0-ph+20),
// ph = row&3 (since (node*1433 + k0) mod 4 == node mod 4; k0 % 16 == 0).
// Row 0 always has ph=0, so no global underflow; window end <= k0+20 <= 1428
// < F on all fast chunks. Boundary chunks/blocks use the predicated 4B path.
__global__ __launch_bounds__(256) void gemm1_kernel(
    const float* __restrict__ x, const float* __restrict__ W1,
    const float* __restrict__ b1, int N, int F)
{
    __shared__ float xs[2][BM * XSW];
    __shared__ float ws[2][BK * 16];

    const int t  = threadIdx.x;
    const int r  = t >> 1;            // 0..127
    const int cg = t & 1;             // col half
    const int n0 = blockIdx.x * BM;
    const int nch = (F + BK - 1) / BK;

    const int wkk = t >> 4, wcc = t & 15;
    const int lrow = t >> 4;          // boundary-loader base row
    const int lcol = t & 15;          // boundary-loader col

    const bool full = (n0 + BM <= N);
    const int myph = t & 3;                        // phase of fast-path row t
    const float* rowbase = x + (size_t)(n0 + t) * F - myph;  // 16B-aligned + k0

    unsigned long long acc0[4], acc1[4];
#pragma unroll
    for (int j = 0; j < 4; j++) { acc0[j] = 0ull; acc1[j] = 0ull; }

    auto issue_chunk = [&](int c, int buf) {
        const int k0 = c * BK;
        if (full && (k0 + BK <= F)) {
            // fast path: 5 x cp16 per thread (each thread owns row t)
            const float* src = rowbase + k0;
            uint32_t dst = smem_u32(&xs[buf][t * XSW]);
#pragma unroll
            for (int sgm = 0; sgm < 5; sgm++) {
                cp16(dst, src);
                src += 4; dst += 16;
            }
            cp4(smem_u32(&ws[buf][t]), W1 + (size_t)(k0 + wkk) * 16 + wcc);
        } else {
            // boundary path: predicated 4B, honoring the phase layout
#pragma unroll
            for (int i = 0; i < 16; i++) {
                int row = lrow + 16 * i;
                int node = n0 + row, k = k0 + lcol;
                bool inb = (node < N) && (k < F);
                const float* src = x + (size_t)(inb ? node : 0) * F + (inb ? k : 0);
                cp4p(smem_u32(&xs[buf][row * XSW + (row & 3) + lcol]), src, inb);
            }
            int kw = k0 + wkk;
            bool winb = (kw < F);
            cp4p(smem_u32(&ws[buf][t]), W1 + (size_t)(winb ? kw : 0) * 16 + wcc, winb);
        }
    };

    issue_chunk(0, 0);
    CP_COMMIT();

    const int xoff0 = r * XSW + (r & 3);               // row r phase offset
    const int xoff1 = (r + 128) * XSW + (r & 3);       // (r+128)&3 == r&3

    for (int c = 0; c < nch; c++) {
        const int cur = c & 1;
        const bool more = (c + 1 < nch);
        if (more) { issue_chunk(c + 1, cur ^ 1); CP_COMMIT(); }
        if (more) asm volatile("cp.async.wait_group 1;" ::: "memory");
        else      asm volatile("cp.async.wait_group 0;" ::: "memory");
        __syncthreads();
#pragma unroll
        for (int kk = 0; kk < BK; kk++) {
            ulonglong2 wA = *(const ulonglong2*)&ws[cur][kk * 16 + cg * 8];
            ulonglong2 wB = *(const ulonglong2*)&ws[cur][kk * 16 + cg * 8 + 4];
            unsigned long long x0 = bcast2(xs[cur][xoff0 + kk]);
            unsigned long long x1 = bcast2(xs[cur][xoff1 + kk]);
            fma2(acc0[0], x0, wA.x); fma2(acc0[1], x0, wA.y);
            fma2(acc0[2], x0, wB.x); fma2(acc0[3], x0, wB.y);
            fma2(acc1[0], x1, wA.x); fma2(acc1[1], x1, wA.y);
            fma2(acc1[2], x1, wB.x); fma2(acc1[3], x1, wB.y);
        }
        __syncthreads();
    }

#pragma unroll
    for (int p = 0; p < 2; p++) {
        int node = n0 + r + 128 * p;
        if (node >= N) continue;
        unsigned long long* acc = p ? acc1 : acc0;
        float2 v0 = unpack2(acc[0]), v1 = unpack2(acc[1]);
        float2 v2 = unpack2(acc[2]), v3 = unpack2(acc[3]);
        float di = g_dinv[node];
        float hs[8] = { v0.x * di, v0.y * di, v1.x * di, v1.y * di,
                        v2.x * di, v2.y * di, v3.x * di, v3.y * di };
        float* hp = (float*)g_h0 + (size_t)node * 16 + cg * 8;
        float* ap = (float*)g_a1 + (size_t)node * 16 + cg * 8;
        *(float4*)hp       = make_float4(hs[0], hs[1], hs[2], hs[3]);
        *(float4*)(hp + 4) = make_float4(hs[4], hs[5], hs[6], hs[7]);
        *(float4*)ap       = make_float4(hs[0] * di + __ldg(&b1[cg * 8 + 0]),
                                         hs[1] * di + __ldg(&b1[cg * 8 + 1]),
                                         hs[2] * di + __ldg(&b1[cg * 8 + 2]),
                                         hs[3] * di + __ldg(&b1[cg * 8 + 3]));
        *(float4*)(ap + 4) = make_float4(hs[4] * di + __ldg(&b1[cg * 8 + 4]),
                                         hs[5] * di + __ldg(&b1[cg * 8 + 5]),
                                         hs[6] * di + __ldg(&b1[cg * 8 + 6]),
                                         hs[7] * di + __ldg(&b1[cg * 8 + 7]));
    }
}

// ---- aggregation: CSR gather, no atomics ----------------------------------

// 4 threads per node; thread q owns float4 column slice q.
__global__ void agg1_kernel(int N) {
    int idx = blockIdx.x * blockDim.x + threadIdx.x;
    int n = idx >> 2;
    int q = idx & 3;
    if (n >= N) return;
    int beg = g_start[n];
    int cnt = g_cnt[n];
    float4 sum = make_float4(0.f, 0.f, 0.f, 0.f);
    for (int j = 0; j < cnt; j++) {
        int s = __ldg(&g_ebuf[beg + j]);
        float4 v = __ldg(&g_h0[(size_t)s * 4 + q]);
        sum.x += v.x; sum.y += v.y; sum.z += v.z; sum.w += v.w;
    }
    float di = g_dinv[n];
    float4* ap = &g_a1[(size_t)n * 4 + q];
    float4 a = *ap;
    a.x += sum.x * di; a.y += sum.y * di;
    a.z += sum.z * di; a.w += sum.w * di;
    *ap = a;
}

// h1s[N,8] = (relu(a1)@W2)*dinv; z = h1s*dinv + b2 (fused).
__global__ void gemm2_kernel(const float* __restrict__ W2,
                             const float* __restrict__ b2, int N) {
    __shared__ float w2s[HID * NCLS];
    int t = threadIdx.x;
    if (t < HID * NCLS) w2s[t] = W2[t];
    __syncthreads();
    int n = blockIdx.x * blockDim.x + t;
    if (n >= N) return;
    const float4* ap = g_a1 + (size_t)n * 4;
    float r[16];
#pragma unroll
    for (int q = 0; q < 4; q++) {
        float4 v = ap[q];
        r[q * 4 + 0] = fmaxf(v.x, 0.f); r[q * 4 + 1] = fmaxf(v.y, 0.f);
        r[q * 4 + 2] = fmaxf(v.z, 0.f); r[q * 4 + 3] = fmaxf(v.w, 0.f);
    }
    float o[NCLS];
#pragma unroll
    for (int c = 0; c < NCLS; c++) o[c] = 0.f;
#pragma unroll
    for (int j = 0; j < 16; j++) {
        float rv = r[j];
#pragma unroll
        for (int c = 0; c < NCLS; c++) o[c] += rv * w2s[j * NCLS + c];
    }
    float di = g_dinv[n];
    float hs[NCLS];
#pragma unroll
    for (int c = 0; c < NCLS; c++) hs[c] = o[c] * di;

    float* hp = (float*)(g_h1 + (size_t)n * 2);
    *(float4*)hp       = make_float4(hs[0], hs[1], hs[2], hs[3]);
    *(float4*)(hp + 4) = make_float4(hs[4], hs[5], hs[6], 0.f);

    float* zp = (float*)(g_z + (size_t)n * 2);
    *(float4*)zp       = make_float4(hs[0] * di + __ldg(&b2[0]), hs[1] * di + __ldg(&b2[1]),
                                     hs[2] * di + __ldg(&b2[2]), hs[3] * di + __ldg(&b2[3]));
    *(float4*)(zp + 4) = make_float4(hs[4] * di + __ldg(&b2[4]), hs[5] * di + __ldg(&b2[5]),
                                     hs[6] * di + __ldg(&b2[6]), 0.f);
}

// 2 threads per node; thread q owns float4 half q of the 8-wide row.
__global__ void agg2_kernel(int N) {
    int idx = blockIdx.x * blockDim.x + threadIdx.x;
    int n = idx >> 1;
    int q = idx & 1;
    if (n >= N) return;
    int beg = g_start[n];
    int cnt = g_cnt[n];
    float4 sum = make_float4(0.f, 0.f, 0.f, 0.f);
    for (int j = 0; j < cnt; j++) {
        int s = __ldg(&g_ebuf[beg + j]);
        float4 v = __ldg(&g_h1[(size_t)s * 2 + q]);
        sum.x += v.x; sum.y += v.y; sum.z += v.z; sum.w += v.w;
    }
    float di = g_dinv[n];
    float4* zp = &g_z[(size_t)n * 2 + q];
    float4 z = *zp;
    z.x += sum.x * di; z.y += sum.y * di;
    z.z += sum.z * di; z.w += sum.w * di;
    *zp = z;
}

// segment_max (via ordered-uint atomicMax) + log_softmax, fused
__global__ void segmax_logsm_kernel(const int* __restrict__ batch,
                                    float* __restrict__ out, int N) {
    int n = blockIdx.x * blockDim.x + threadIdx.x;
    if (n >= N) return;
    const float* zp = (const float*)(g_z + (size_t)n * 2);
    float4 z0 = *(const float4*)zp;
    float4 z1 = *(const float4*)(zp + 4);
    float zz[NCLS] = { z0.x, z0.y, z0.z, z0.w, z1.x, z1.y, z1.z };

    int b = batch[n];
#pragma unroll
    for (int c = 0; c < NCLS; c++)
        atomicMax(&g_gkey[b * NCLS + c], fkey(zz[c]));

    float m = zz[0];
#pragma unroll
    for (int c = 1; c < NCLS; c++) m = fmaxf(m, zz[c]);
    float s = 0.f;
#pragma unroll
    for (int c = 0; c < NCLS; c++) s += expf(zz[c] - m);
    float ls = m + logf(s);
    float* op = out + NUM_GRAPHS * NCLS + (size_t)n * NCLS;
#pragma unroll
    for (int c = 0; c < NCLS; c++) op[c] = zz[c] - ls;
}

__global__ void decode_g_kernel(float* __restrict__ out) {
    int j = threadIdx.x;
    if (j < NUM_GRAPHS * NCLS) out[j] = funkey(g_gkey[j]);
}

// ---------------------------------------------------------------------------

extern "C" void kernel_launch(void* const* d_in, const int* in_sizes, int n_in,
                              void* d_out, int out_size) {
    const float* x     = (const float*)d_in[0];
    const int*   ei    = (const int*)d_in[1];
    const int*   batch = (const int*)d_in[2];
    const float* W1    = (const float*)d_in[3];
    const float* b1    = (const float*)d_in[4];
    const float* W2    = (const float*)d_in[5];
    const float* b2    = (const float*)d_in[6];
    float* out = (float*)d_out;

    const int N = in_sizes[2];
    const int F = in_sizes[0] / N;
    const int E = in_sizes[1] / 2;

    const int nbN = (N + 255) / 256;
    const int nbE = (E + 255) / 256;

    zero_kernel<<<nbN, 256>>>(N);
    count_kernel<<<nbE, 256>>>(ei, E);
    scan_kernel<<<nbN, 256>>>(N);
    scatter_kernel<<<nbE, 256>>>(ei, E);

    gemm1_kernel<<<(N + BM - 1) / BM, 256>>>(x, W1, b1, N, F);
    agg1_kernel<<<(4 * N + 255) / 256, 256>>>(N);

    gemm2_kernel<<<nbN, 256>>>(W2, b2, N);
    agg2_kernel<<<(2 * N + 255) / 256, 256>>>(N);

    segmax_logsm_kernel<<<nbN, 256>>>(batch, out, N);
    decode_g_kernel<<<1, 512>>>(out);
}

// round 14
// speedup vs baseline: 1.1120x; 1.1120x over previous
#include <cuda_runtime.h>
#include <cuda_bf16.h>
#include <cstdint>

// ---------------------------------------------------------------------------
// GCN 2-layer: h = relu(GCNConv(x,W1,b1)); z = GCNConv(h,W2,b2)
// out = [ segment_max(z,batch) (64x7) ; log_softmax(z) (Nx7) ]
// edge_index/batch are int32. No tcgen05 (compute_103 PTX target).
// GEMM1: cp.async 16B loader, 5-threads-per-row coalesced mapping + FFMA2.
// Aggregation: CSR gather (rank captured during count -> atomic-free scatter).
// ---------------------------------------------------------------------------

#define MAXN 100352
#define MAXE 3356672
#define NUM_GRAPHS 64
#define HID 16
#define NCLS 7
#define BM 256       // nodes per CTA in gemm1
#define BK 16        // k-chunk
#define XSW 20       // smem row stride (floats) in gemm1

// ---- scratch (device globals; no allocation allowed) ----------------------
__device__ int      g_cnt[MAXN];      // in-degree (no self-loop)
__device__ int      g_start[MAXN];    // CSR segment start
__device__ int      g_rank[MAXE];     // per-edge rank within its dst segment
__device__ int      g_ebuf[MAXE];     // src indices grouped by dst
__device__ int      g_total;
__device__ float    g_dinv[MAXN];
__device__ float4   g_h0[MAXN * 4];   // [N][16]  (x@W1) * dinv  (pre-scaled)
__device__ float4   g_a1[MAXN * 4];   // [N][16]  aggregated + b1
__device__ float4   g_h1[MAXN * 2];   // [N][8]   (relu(a1)@W2) * dinv (pre-scaled)
__device__ float4   g_z [MAXN * 2];   // [N][8]   aggregated z
__device__ unsigned g_gkey[NUM_GRAPHS * NCLS];

// ---- helpers --------------------------------------------------------------

__device__ __forceinline__ unsigned fkey(float f) {
    unsigned u = __float_as_uint(f);
    return (u & 0x80000000u) ? ~u : (u | 0x80000000u);
}
__device__ __forceinline__ float funkey(unsigned u) {
    return __uint_as_float((u & 0x80000000u) ? (u ^ 0x80000000u) : ~u);
}

__device__ __forceinline__ uint32_t smem_u32(const void* p) {
    return (uint32_t)__cvta_generic_to_shared(p);
}
__device__ __forceinline__ void cp16(uint32_t dst, const float* src) {
    asm volatile("cp.async.ca.shared.global [%0], [%1], 16;"
                 :: "r"(dst), "l"(src) : "memory");
}
__device__ __forceinline__ void cp4(uint32_t dst, const float* src) {
    asm volatile("cp.async.ca.shared.global [%0], [%1], 4;"
                 :: "r"(dst), "l"(src) : "memory");
}
__device__ __forceinline__ void cp4p(uint32_t dst, const float* src, bool inb) {
    int sz = inb ? 4 : 0;
    asm volatile("cp.async.ca.shared.global [%0], [%1], 4, %2;"
                 :: "r"(dst), "l"(src), "r"(sz) : "memory");
}
#define CP_COMMIT() asm volatile("cp.async.commit_group;" ::: "memory")

// packed fp32x2 (Blackwell FFMA2; bit-identical per-lane fp32)
__device__ __forceinline__ void fma2(unsigned long long& d,
                                     unsigned long long a, unsigned long long b) {
    asm("fma.rn.f32x2 %0, %1, %2, %3;" : "=l"(d) : "l"(a), "l"(b), "l"(d));
}
__device__ __forceinline__ unsigned long long bcast2(float v) {
    unsigned long long r;
    asm("mov.b64 %0, {%1, %1};" : "=l"(r) : "f"(v));
    return r;
}
__device__ __forceinline__ float2 unpack2(unsigned long long v) {
    float lo, hi;
    asm("mov.b64 {%0, %1}, %2;" : "=f"(lo), "=f"(hi) : "l"(v));
    return make_float2(lo, hi);
}

// ---- CSR construction -----------------------------------------------------

__global__ void zero_kernel(int N) {
    int i = blockIdx.x * blockDim.x + threadIdx.x;
    if (i < N) g_cnt[i] = 0;
    if (i < NUM_GRAPHS * NCLS) g_gkey[i] = 0u;
    if (i == 0) g_total = 0;
}

// count in-degree AND capture each edge's rank within its dst segment
__global__ void count_kernel(const int* __restrict__ ei, int E) {
    int e = blockIdx.x * blockDim.x + threadIdx.x;
    if (e >= E) return;
    g_rank[e] = atomicAdd(&g_cnt[ei[E + e]], 1);
}

// block-scan of counts -> per-node segment start + dinv
__global__ void scan_kernel(int N) {
    __shared__ int sdata[256];
    __shared__ int base;
    int tid = threadIdx.x;
    int n = blockIdx.x * 256 + tid;
    int c = (n < N) ? g_cnt[n] : 0;
    sdata[tid] = c;
    __syncthreads();
#pragma unroll
    for (int off = 1; off < 256; off <<= 1) {
        int v = (tid >= off) ? sdata[tid - off] : 0;
        __syncthreads();
        sdata[tid] += v;
        __syncthreads();
    }
    if (tid == 255) base = atomicAdd(&g_total, sdata[255]);
    __syncthreads();
    if (n < N) {
        g_start[n] = base + sdata[tid] - c;
        g_dinv[n]  = rsqrtf((float)(c + 1));   // +1 self-loop
    }
}

// atomic-free scatter using captured ranks
__global__ void scatter_kernel(const int* __restrict__ ei, int E) {
    int e = blockIdx.x * blockDim.x + threadIdx.x;
    if (e >= E) return;
    int s = ei[e];
    int d = ei[E + e];
    g_ebuf[g_start[d] + g_rank[e]] = s;
}

// ---- GEMM1: h0s[N,16] = (x@W1)*dinv; a1 = h0s*dinv + b1 (fused) -----------
// Fast path: per row a 16B-aligned 20-float window [k0-ph, k0-ph+20),
// ph = row&3. 1280 cp16s mapped as idx = t + 256*i, row = idx/5, seg = idx%5:
// 5 consecutive threads cover one row's contiguous 80B -> coalesced warps.
// Row 0 has ph=0 (no underflow); window end <= k0+20 <= 1428 < F on fast
// chunks. Boundary chunks/blocks use the predicated 4B path.
__global__ __launch_bounds__(256) void gemm1_kernel(
    const float* __restrict__ x, const float* __restrict__ W1,
    const float* __restrict__ b1, int N, int F)
{
    __shared__ float xs[2][BM * XSW];
    __shared__ float ws[2][BK * 16];

    const int t  = threadIdx.x;
    const int r  = t >> 1;            // 0..127
    const int cg = t & 1;             // col half
    const int n0 = blockIdx.x * BM;
    const int nch = (F + BK - 1) / BK;

    const int wkk = t >> 4, wcc = t & 15;
    const int lrow = t >> 4;          // boundary-loader base row
    const int lcol = t & 15;          // boundary-loader col

    const bool full = (n0 + BM <= N);

    // precompute the 5 (row, seg) pairs for this thread's cp16s
    int c16row[5], c16seg[5];
#pragma unroll
    for (int i = 0; i < 5; i++) {
        unsigned idx = (unsigned)(t + 256 * i);
        unsigned row = (idx * 13108u) >> 16;   // idx/5, exact for idx < 1280
        c16row[i] = (int)row;
        c16seg[i] = (int)(idx - row * 5u);
    }

    unsigned long long acc0[4], acc1[4];
#pragma unroll
    for (int j = 0; j < 4; j++) { acc0[j] = 0ull; acc1[j] = 0ull; }

    auto issue_chunk = [&](int c, int buf) {
        const int k0 = c * BK;
        if (full && (k0 + BK <= F)) {
            // fast path: 5 cp16 per thread, 5 threads cover one row's 80B
#pragma unroll
            for (int i = 0; i < 5; i++) {
                int row = c16row[i], seg = c16seg[i];
                int ph = row & 3;
                const float* src = x + (size_t)(n0 + row) * F + (k0 - ph + seg * 4);
                cp16(smem_u32(&xs[buf][row * XSW + seg * 4]), src);
            }
            cp4(smem_u32(&ws[buf][t]), W1 + (size_t)(k0 + wkk) * 16 + wcc);
        } else {
            // boundary path: predicated 4B, honoring the phase layout
#pragma unroll
            for (int i = 0; i < 16; i++) {
                int row = lrow + 16 * i;
                int node = n0 + row, k = k0 + lcol;
                bool inb = (node < N) && (k < F);
                const float* src = x + (size_t)(inb ? node : 0) * F + (inb ? k : 0);
                cp4p(smem_u32(&xs[buf][row * XSW + (row & 3) + lcol]), src, inb);
            }
            int kw = k0 + wkk;
            bool winb = (kw < F);
            cp4p(smem_u32(&ws[buf][t]), W1 + (size_t)(winb ? kw : 0) * 16 + wcc, winb);
        }
    };

    issue_chunk(0, 0);
    CP_COMMIT();

    const int xoff0 = r * XSW + (r & 3);               // row r phase offset
    const int xoff1 = (r + 128) * XSW + (r & 3);       // (r+128)&3 == r&3

    for (int c = 0; c < nch; c++) {
        const int cur = c & 1;
        const bool more = (c + 1 < nch);
        if (more) { issue_chunk(c + 1, cur ^ 1); CP_COMMIT(); }
        if (more) asm volatile("cp.async.wait_group 1;" ::: "memory");
        else      asm volatile("cp.async.wait_group 0;" ::: "memory");
        __syncthreads();
#pragma unroll
        for (int kk = 0; kk < BK; kk++) {
            ulonglong2 wA = *(const ulonglong2*)&ws[cur][kk * 16 + cg * 8];
            ulonglong2 wB = *(const ulonglong2*)&ws[cur][kk * 16 + cg * 8 + 4];
            unsigned long long x0 = bcast2(xs[cur][xoff0 + kk]);
            unsigned long long x1 = bcast2(xs[cur][xoff1 + kk]);
            fma2(acc0[0], x0, wA.x); fma2(acc0[1], x0, wA.y);
            fma2(acc0[2], x0, wB.x); fma2(acc0[3], x0, wB.y);
            fma2(acc1[0], x1, wA.x); fma2(acc1[1], x1, wA.y);
            fma2(acc1[2], x1, wB.x); fma2(acc1[3], x1, wB.y);
        }
        __syncthreads();
    }

#pragma unroll
    for (int p = 0; p < 2; p++) {
        int node = n0 + r + 128 * p;
        if (node >= N) continue;
        unsigned long long* acc = p ? acc1 : acc0;
        float2 v0 = unpack2(acc[0]), v1 = unpack2(acc[1]);
        float2 v2 = unpack2(acc[2]), v3 = unpack2(acc[3]);
        float di = g_dinv[node];
        float hs[8] = { v0.x * di, v0.y * di, v1.x * di, v1.y * di,
                        v2.x * di, v2.y * di, v3.x * di, v3.y * di };
        float* hp = (float*)g_h0 + (size_t)node * 16 + cg * 8;
        float* ap = (float*)g_a1 + (size_t)node * 16 + cg * 8;
        *(float4*)hp       = make_float4(hs[0], hs[1], hs[2], hs[3]);
        *(float4*)(hp + 4) = make_float4(hs[4], hs[5], hs[6], hs[7]);
        *(float4*)ap       = make_float4(hs[0] * di + __ldg(&b1[cg * 8 + 0]),
                                         hs[1] * di + __ldg(&b1[cg * 8 + 1]),
                                         hs[2] * di + __ldg(&b1[cg * 8 + 2]),
                                         hs[3] * di + __ldg(&b1[cg * 8 + 3]));
        *(float4*)(ap + 4) = make_float4(hs[4] * di + __ldg(&b1[cg * 8 + 4]),
                                         hs[5] * di + __ldg(&b1[cg * 8 + 5]),
                                         hs[6] * di + __ldg(&b1[cg * 8 + 6]),
                                         hs[7] * di + __ldg(&b1[cg * 8 + 7]));
    }
}

// ---- aggregation: CSR gather, no atomics ----------------------------------

// 4 threads per node; thread q owns float4 column slice q.
__global__ void agg1_kernel(int N) {
    int idx = blockIdx.x * blockDim.x + threadIdx.x;
    int n = idx >> 2;
    int q = idx & 3;
    if (n >= N) return;
    int beg = g_start[n];
    int cnt = g_cnt[n];
    float4 sum = make_float4(0.f, 0.f, 0.f, 0.f);
    for (int j = 0; j < cnt; j++) {
        int s = __ldg(&g_ebuf[beg + j]);
        float4 v = __ldg(&g_h0[(size_t)s * 4 + q]);
        sum.x += v.x; sum.y += v.y; sum.z += v.z; sum.w += v.w;
    }
    float di = g_dinv[n];
    float4* ap = &g_a1[(size_t)n * 4 + q];
    float4 a = *ap;
    a.x += sum.x * di; a.y += sum.y * di;
    a.z += sum.z * di; a.w += sum.w * di;
    *ap = a;
}

// h1s[N,8] = (relu(a1)@W2)*dinv; z = h1s*dinv + b2 (fused).
__global__ void gemm2_kernel(const float* __restrict__ W2,
                             const float* __restrict__ b2, int N) {
    __shared__ float w2s[HID * NCLS];
    int t = threadIdx.x;
    if (t < HID * NCLS) w2s[t] = W2[t];
    __syncthreads();
    int n = blockIdx.x * blockDim.x + t;
    if (n >= N) return;
    const float4* ap = g_a1 + (size_t)n * 4;
    float r[16];
#pragma unroll
    for (int q = 0; q < 4; q++) {
        float4 v = ap[q];
        r[q * 4 + 0] = fmaxf(v.x, 0.f); r[q * 4 + 1] = fmaxf(v.y, 0.f);
        r[q * 4 + 2] = fmaxf(v.z, 0.f); r[q * 4 + 3] = fmaxf(v.w, 0.f);
    }
    float o[NCLS];
#pragma unroll
    for (int c = 0; c < NCLS; c++) o[c] = 0.f;
#pragma unroll
    for (int j = 0; j < 16; j++) {
        float rv = r[j];
#pragma unroll
        for (int c = 0; c < NCLS; c++) o[c] += rv * w2s[j * NCLS + c];
    }
    float di = g_dinv[n];
    float hs[NCLS];
#pragma unroll
    for (int c = 0; c < NCLS; c++) hs[c] = o[c] * di;

    float* hp = (float*)(g_h1 + (size_t)n * 2);
    *(float4*)hp       = make_float4(hs[0], hs[1], hs[2], hs[3]);
    *(float4*)(hp + 4) = make_float4(hs[4], hs[5], hs[6], 0.f);

    float* zp = (float*)(g_z + (size_t)n * 2);
    *(float4*)zp       = make_float4(hs[0] * di + __ldg(&b2[0]), hs[1] * di + __ldg(&b2[1]),
                                     hs[2] * di + __ldg(&b2[2]), hs[3] * di + __ldg(&b2[3]));
    *(float4*)(zp + 4) = make_float4(hs[4] * di + __ldg(&b2[4]), hs[5] * di + __ldg(&b2[5]),
                                     hs[6] * di + __ldg(&b2[6]), 0.f);
}

// 2 threads per node; thread q owns float4 half q of the 8-wide row.
__global__ void agg2_kernel(int N) {
    int idx = blockIdx.x * blockDim.x + threadIdx.x;
    int n = idx >> 1;
    int q = idx & 1;
    if (n >= N) return;
    int beg = g_start[n];
    int cnt = g_cnt[n];
    float4 sum = make_float4(0.f, 0.f, 0.f, 0.f);
    for (int j = 0; j < cnt; j++) {
        int s = __ldg(&g_ebuf[beg + j]);
        float4 v = __ldg(&g_h1[(size_t)s * 2 + q]);
        sum.x += v.x; sum.y += v.y; sum.z += v.z; sum.w += v.w;
    }
    float di = g_dinv[n];
    float4* zp = &g_z[(size_t)n * 2 + q];
    float4 z = *zp;
    z.x += sum.x * di; z.y += sum.y * di;
    z.z += sum.z * di; z.w += sum.w * di;
    *zp = z;
}

// segment_max (via ordered-uint atomicMax) + log_softmax, fused
__global__ void segmax_logsm_kernel(const int* __restrict__ batch,
                                    float* __restrict__ out, int N) {
    int n = blockIdx.x * blockDim.x + threadIdx.x;
    if (n >= N) return;
    const float* zp = (const float*)(g_z + (size_t)n * 2);
    float4 z0 = *(const float4*)zp;
    float4 z1 = *(const float4*)(zp + 4);
    float zz[NCLS] = { z0.x, z0.y, z0.z, z0.w, z1.x, z1.y, z1.z };

    int b = batch[n];
#pragma unroll
    for (int c = 0; c < NCLS; c++)
        atomicMax(&g_gkey[b * NCLS + c], fkey(zz[c]));

    float m = zz[0];
#pragma unroll
    for (int c = 1; c < NCLS; c++) m = fmaxf(m, zz[c]);
    float s = 0.f;
#pragma unroll
    for (int c = 0; c < NCLS; c++) s += expf(zz[c] - m);
    float ls = m + logf(s);
    float* op = out + NUM_GRAPHS * NCLS + (size_t)n * NCLS;
#pragma unroll
    for (int c = 0; c < NCLS; c++) op[c] = zz[c] - ls;
}

__global__ void decode_g_kernel(float* __restrict__ out) {
    int j = threadIdx.x;
    if (j < NUM_GRAPHS * NCLS) out[j] = funkey(g_gkey[j]);
}

// ---------------------------------------------------------------------------

extern "C" void kernel_launch(void* const* d_in, const int* in_sizes, int n_in,
                              void* d_out, int out_size) {
    const float* x     = (const float*)d_in[0];
    const int*   ei    = (const int*)d_in[1];
    const int*   batch = (const int*)d_in[2];
    const float* W1    = (const float*)d_in[3];
    const float* b1    = (const float*)d_in[4];
    const float* W2    = (const float*)d_in[5];
    const float* b2    = (const float*)d_in[6];
    float* out = (float*)d_out;

    const int N = in_sizes[2];
    const int F = in_sizes[0] / N;
    const int E = in_sizes[1] / 2;

    const int nbN = (N + 255) / 256;
    const int nbE = (E + 255) / 256;

    zero_kernel<<<nbN, 256>>>(N);
    count_kernel<<<nbE, 256>>>(ei, E);
    scan_kernel<<<nbN, 256>>>(N);
    scatter_kernel<<<nbE, 256>>>(ei, E);

    gemm1_kernel<<<(N + BM - 1) / BM, 256>>>(x, W1, b1, N, F);
    agg1_kernel<<<(4 * N + 255) / 256, 256>>>(N);

    gemm2_kernel<<<nbN, 256>>>(W2, b2, N);
    agg2_kernel<<<(2 * N + 255) / 256, 256>>>(N);

    segmax_logsm_kernel<<<nbN, 256>>>(batch, out, N);
    decode_g_kernel<<<1, 512>>>(out);
}

// round 15
// speedup vs baseline: 1.1711x; 1.0531x over previous
#include <cuda_runtime.h>
#include <cuda_bf16.h>
#include <cstdint>

// ---------------------------------------------------------------------------
// GCN 2-layer: h = relu(GCNConv(x,W1,b1)); z = GCNConv(h,W2,b2)
// out = [ segment_max(z,batch) (64x7) ; log_softmax(z) (Nx7) ]
// edge_index/batch are int32. No tcgen05 (compute_103 PTX target).
// GEMM1: R12 loader (4B cp.async, coalesced, strength-reduced) + FFMA2.
// Aggregation: CSR gather (rank captured during count -> atomic-free scatter).
// ---------------------------------------------------------------------------

#define MAXN 100352
#define MAXE 3356672
#define NUM_GRAPHS 64
#define HID 16
#define NCLS 7
#define BM 256       // nodes per CTA in gemm1
#define BK 16        // k-chunk

// ---- scratch (device globals; no allocation allowed) ----------------------
__device__ int      g_cnt[MAXN];      // in-degree (no self-loop)
__device__ int      g_start[MAXN];    // CSR segment start
__device__ int      g_rank[MAXE];     // per-edge rank within its dst segment
__device__ int      g_ebuf[MAXE];     // src indices grouped by dst
__device__ int      g_total;
__device__ float    g_dinv[MAXN];
__device__ float4   g_h0[MAXN * 4];   // [N][16]  (x@W1) * dinv  (pre-scaled)
__device__ float4   g_a1[MAXN * 4];   // [N][16]  aggregated + b1
__device__ float4   g_h1[MAXN * 2];   // [N][8]   (relu(a1)@W2) * dinv (pre-scaled)
__device__ float4   g_z [MAXN * 2];   // [N][8]   aggregated z
__device__ unsigned g_gkey[NUM_GRAPHS * NCLS];

// ---- helpers --------------------------------------------------------------

__device__ __forceinline__ unsigned fkey(float f) {
    unsigned u = __float_as_uint(f);
    return (u & 0x80000000u) ? ~u : (u | 0x80000000u);
}
__device__ __forceinline__ float funkey(unsigned u) {
    return __uint_as_float((u & 0x80000000u) ? (u ^ 0x80000000u) : ~u);
}

__device__ __forceinline__ uint32_t smem_u32(const void* p) {
    return (uint32_t)__cvta_generic_to_shared(p);
}
__device__ __forceinline__ void cp4(uint32_t dst, const float* src) {
    asm volatile("cp.async.ca.shared.global [%0], [%1], 4;"
                 :: "r"(dst), "l"(src) : "memory");
}
__device__ __forceinline__ void cp4p(uint32_t dst, const float* src, bool inb) {
    int sz = inb ? 4 : 0;
    asm volatile("cp.async.ca.shared.global [%0], [%1], 4, %2;"
                 :: "r"(dst), "l"(src), "r"(sz) : "memory");
}
#define CP_COMMIT() asm volatile("cp.async.commit_group;" ::: "memory")

// packed fp32x2 (Blackwell FFMA2; bit-identical per-lane fp32)
__device__ __forceinline__ void fma2(unsigned long long& d,
                                     unsigned long long a, unsigned long long b) {
    asm("fma.rn.f32x2 %0, %1, %2, %3;" : "=l"(d) : "l"(a), "l"(b), "l"(d));
}
__device__ __forceinline__ unsigned long long bcast2(float v) {
    unsigned long long r;
    asm("mov.b64 %0, {%1, %1};" : "=l"(r) : "f"(v));
    return r;
}
__device__ __forceinline__ float2 unpack2(unsigned long long v) {
    float lo, hi;
    asm("mov.b64 {%0, %1}, %2;" : "=f"(lo), "=f"(hi) : "l"(v));
    return make_float2(lo, hi);
}

// ---- CSR construction -----------------------------------------------------

__global__ void zero_kernel(int N) {
    int i = blockIdx.x * blockDim.x + threadIdx.x;
    if (i < N) g_cnt[i] = 0;
    if (i < NUM_GRAPHS * NCLS) g_gkey[i] = 0u;
    if (i == 0) g_total = 0;
}

// count in-degree AND capture each edge's rank within its dst segment
__global__ void count_kernel(const int* __restrict__ ei, int E) {
    int e = blockIdx.x * blockDim.x + threadIdx.x;
    if (e >= E) return;
    g_rank[e] = atomicAdd(&g_cnt[ei[E + e]], 1);
}

// block-scan of counts -> per-node segment start + dinv
__global__ void scan_kernel(int N) {
    __shared__ int sdata[256];
    __shared__ int base;
    int tid = threadIdx.x;
    int n = blockIdx.x * 256 + tid;
    int c = (n < N) ? g_cnt[n] : 0;
    sdata[tid] = c;
    __syncthreads();
#pragma unroll
    for (int off = 1; off < 256; off <<= 1) {
        int v = (tid >= off) ? sdata[tid - off] : 0;
        __syncthreads();
        sdata[tid] += v;
        __syncthreads();
    }
    if (tid == 255) base = atomicAdd(&g_total, sdata[255]);
    __syncthreads();
    if (n < N) {
        g_start[n] = base + sdata[tid] - c;
        g_dinv[n]  = rsqrtf((float)(c + 1));   // +1 self-loop
    }
}

// atomic-free scatter using captured ranks
__global__ void scatter_kernel(const int* __restrict__ ei, int E) {
    int e = blockIdx.x * blockDim.x + threadIdx.x;
    if (e >= E) return;
    int s = ei[e];
    int d = ei[E + e];
    g_ebuf[g_start[d] + g_rank[e]] = s;
}

// ---- GEMM1: h0s[N,16] = (x@W1)*dinv; a1 = h0s*dinv + b1 (fused) -----------
// 256 threads, 256-node tile; thread = nodes {r, r+128} x col-half cg.
// cp.async 4B coalesced loader (warp = 2 rows x 64B contiguous), double-
// buffered; fast path strength-reduced, boundary path predicated.
__global__ __launch_bounds__(256) void gemm1_kernel(
    const float* __restrict__ x, const float* __restrict__ W1,
    const float* __restrict__ b1, int N, int F)
{
    __shared__ float xs[2][BM * 17];
    __shared__ float ws[2][BK * 16];

    const int t  = threadIdx.x;
    const int r  = t >> 1;            // 0..127
    const int cg = t & 1;             // col half
    const int n0 = blockIdx.x * BM;
    const int nch = (F + BK - 1) / BK;

    const int wkk = t >> 4, wcc = t & 15;
    const int lrow = t >> 4;          // loader base row
    const int lcol = t & 15;          // loader col

    const bool full = (n0 + BM <= N);
    const float* tb = x + (size_t)(n0 + lrow) * F + lcol;
    const size_t rstep = (size_t)16 * F;

    unsigned long long acc0[4], acc1[4];
#pragma unroll
    for (int j = 0; j < 4; j++) { acc0[j] = 0ull; acc1[j] = 0ull; }

    auto issue_chunk = [&](int c, int buf) {
        const int k0 = c * BK;
        if (full && (k0 + BK <= F)) {
            const float* src = tb + k0;
#pragma unroll
            for (int i = 0; i < 16; i++) {
                cp4(smem_u32(&xs[buf][(lrow + 16 * i) * 17 + lcol]), src);
                src += rstep;
            }
            cp4(smem_u32(&ws[buf][t]), W1 + (size_t)(k0 + wkk) * 16 + wcc);
        } else {
#pragma unroll
            for (int i = 0; i < 16; i++) {
                int row = lrow + 16 * i;
                int node = n0 + row, k = k0 + lcol;
                bool inb = (node < N) && (k < F);
                const float* src = x + (size_t)(inb ? node : 0) * F + (inb ? k : 0);
                cp4p(smem_u32(&xs[buf][row * 17 + lcol]), src, inb);
            }
            int kw = k0 + wkk;
            bool winb = (kw < F);
            cp4p(smem_u32(&ws[buf][t]), W1 + (size_t)(winb ? kw : 0) * 16 + wcc, winb);
        }
    };

    issue_chunk(0, 0);
    CP_COMMIT();

    for (int c = 0; c < nch; c++) {
        const int cur = c & 1;
        const bool more = (c + 1 < nch);
        if (more) { issue_chunk(c + 1, cur ^ 1); CP_COMMIT(); }
        if (more) asm volatile("cp.async.wait_group 1;" ::: "memory");
        else      asm volatile("cp.async.wait_group 0;" ::: "memory");
        __syncthreads();
#pragma unroll
        for (int kk = 0; kk < BK; kk++) {
            ulonglong2 wA = *(const ulonglong2*)&ws[cur][kk * 16 + cg * 8];
            ulonglong2 wB = *(const ulonglong2*)&ws[cur][kk * 16 + cg * 8 + 4];
            unsigned long long x0 = bcast2(xs[cur][r * 17 + kk]);
            unsigned long long x1 = bcast2(xs[cur][(r + 128) * 17 + kk]);
            fma2(acc0[0], x0, wA.x); fma2(acc0[1], x0, wA.y);
            fma2(acc0[2], x0, wB.x); fma2(acc0[3], x0, wB.y);
            fma2(acc1[0], x1, wA.x); fma2(acc1[1], x1, wA.y);
            fma2(acc1[2], x1, wB.x); fma2(acc1[3], x1, wB.y);
        }
        __syncthreads();
    }

#pragma unroll
    for (int p = 0; p < 2; p++) {
        int node = n0 + r + 128 * p;
        if (node >= N) continue;
        unsigned long long* acc = p ? acc1 : acc0;
        float2 v0 = unpack2(acc[0]), v1 = unpack2(acc[1]);
        float2 v2 = unpack2(acc[2]), v3 = unpack2(acc[3]);
        float di = g_dinv[node];
        float hs[8] = { v0.x * di, v0.y * di, v1.x * di, v1.y * di,
                        v2.x * di, v2.y * di, v3.x * di, v3.y * di };
        float* hp = (float*)g_h0 + (size_t)node * 16 + cg * 8;
        float* ap = (float*)g_a1 + (size_t)node * 16 + cg * 8;
        *(float4*)hp       = make_float4(hs[0], hs[1], hs[2], hs[3]);
        *(float4*)(hp + 4) = make_float4(hs[4], hs[5], hs[6], hs[7]);
        *(float4*)ap       = make_float4(hs[0] * di + __ldg(&b1[cg * 8 + 0]),
                                         hs[1] * di + __ldg(&b1[cg * 8 + 1]),
                                         hs[2] * di + __ldg(&b1[cg * 8 + 2]),
                                         hs[3] * di + __ldg(&b1[cg * 8 + 3]));
        *(float4*)(ap + 4) = make_float4(hs[4] * di + __ldg(&b1[cg * 8 + 4]),
                                         hs[5] * di + __ldg(&b1[cg * 8 + 5]),
                                         hs[6] * di + __ldg(&b1[cg * 8 + 6]),
                                         hs[7] * di + __ldg(&b1[cg * 8 + 7]));
    }
}

// ---- aggregation: CSR gather, no atomics ----------------------------------

// 4 threads per node; thread q owns float4 column slice q.
__global__ void agg1_kernel(int N) {
    int idx = blockIdx.x * blockDim.x + threadIdx.x;
    int n = idx >> 2;
    int q = idx & 3;
    if (n >= N) return;
    int beg = g_start[n];
    int cnt = g_cnt[n];
    float4 sum = make_float4(0.f, 0.f, 0.f, 0.f);
    for (int j = 0; j < cnt; j++) {
        int s = __ldg(&g_ebuf[beg + j]);
        float4 v = __ldg(&g_h0[(size_t)s * 4 + q]);
        sum.x += v.x; sum.y += v.y; sum.z += v.z; sum.w += v.w;
    }
    float di = g_dinv[n];
    float4* ap = &g_a1[(size_t)n * 4 + q];
    float4 a = *ap;
    a.x += sum.x * di; a.y += sum.y * di;
    a.z += sum.z * di; a.w += sum.w * di;
    *ap = a;
}

// h1s[N,8] = (relu(a1)@W2)*dinv; z = h1s*dinv + b2 (fused).
__global__ void gemm2_kernel(const float* __restrict__ W2,
                             const float* __restrict__ b2, int N) {
    __shared__ float w2s[HID * NCLS];
    int t = threadIdx.x;
    if (t < HID * NCLS) w2s[t] = W2[t];
    __syncthreads();
    int n = blockIdx.x * blockDim.x + t;
    if (n >= N) return;
    const float4* ap = g_a1 + (size_t)n * 4;
    float r[16];
#pragma unroll
    for (int q = 0; q < 4; q++) {
        float4 v = ap[q];
        r[q * 4 + 0] = fmaxf(v.x, 0.f); r[q * 4 + 1] = fmaxf(v.y, 0.f);
        r[q * 4 + 2] = fmaxf(v.z, 0.f); r[q * 4 + 3] = fmaxf(v.w, 0.f);
    }
    float o[NCLS];
#pragma unroll
    for (int c = 0; c < NCLS; c++) o[c] = 0.f;
#pragma unroll
    for (int j = 0; j < 16; j++) {
        float rv = r[j];
#pragma unroll
        for (int c = 0; c < NCLS; c++) o[c] += rv * w2s[j * NCLS + c];
    }
    float di = g_dinv[n];
    float hs[NCLS];
#pragma unroll
    for (int c = 0; c < NCLS; c++) hs[c] = o[c] * di;

    float* hp = (float*)(g_h1 + (size_t)n * 2);
    *(float4*)hp       = make_float4(hs[0], hs[1], hs[2], hs[3]);
    *(float4*)(hp + 4) = make_float4(hs[4], hs[5], hs[6], 0.f);

    float* zp = (float*)(g_z + (size_t)n * 2);
    *(float4*)zp       = make_float4(hs[0] * di + __ldg(&b2[0]), hs[1] * di + __ldg(&b2[1]),
                                     hs[2] * di + __ldg(&b2[2]), hs[3] * di + __ldg(&b2[3]));
    *(float4*)(zp + 4) = make_float4(hs[4] * di + __ldg(&b2[4]), hs[5] * di + __ldg(&b2[5]),
                                     hs[6] * di + __ldg(&b2[6]), 0.f);
}

// 2 threads per node; thread q owns float4 half q of the 8-wide row.
__global__ void agg2_kernel(int N) {
    int idx = blockIdx.x * blockDim.x + threadIdx.x;
    int n = idx >> 1;
    int q = idx & 1;
    if (n >= N) return;
    int beg = g_start[n];
    int cnt = g_cnt[n];
    float4 sum = make_float4(0.f, 0.f, 0.f, 0.f);
    for (int j = 0; j < cnt; j++) {
        int s = __ldg(&g_ebuf[beg + j]);
        float4 v = __ldg(&g_h1[(size_t)s * 2 + q]);
        sum.x += v.x; sum.y += v.y; sum.z += v.z; sum.w += v.w;
    }
    float di = g_dinv[n];
    float4* zp = &g_z[(size_t)n * 2 + q];
    float4 z = *zp;
    z.x += sum.x * di; z.y += sum.y * di;
    z.z += sum.z * di; z.w += sum.w * di;
    *zp = z;
}

// segment_max (via ordered-uint atomicMax) + log_softmax, fused
__global__ void segmax_logsm_kernel(const int* __restrict__ batch,
                                    float* __restrict__ out, int N) {
    int n = blockIdx.x * blockDim.x + threadIdx.x;
    if (n >= N) return;
    const float* zp = (const float*)(g_z + (size_t)n * 2);
    float4 z0 = *(const float4*)zp;
    float4 z1 = *(const float4*)(zp + 4);
    float zz[NCLS] = { z0.x, z0.y, z0.z, z0.w, z1.x, z1.y, z1.z };

    int b = batch[n];
#pragma unroll
    for (int c = 0; c < NCLS; c++)
        atomicMax(&g_gkey[b * NCLS + c], fkey(zz[c]));

    float m = zz[0];
#pragma unroll
    for (int c = 1; c < NCLS; c++) m = fmaxf(m, zz[c]);
    float s = 0.f;
#pragma unroll
    for (int c = 0; c < NCLS; c++) s += expf(zz[c] - m);
    float ls = m + logf(s);
    float* op = out + NUM_GRAPHS * NCLS + (size_t)n * NCLS;
#pragma unroll
    for (int c = 0; c < NCLS; c++) op[c] = zz[c] - ls;
}

__global__ void decode_g_kernel(float* __restrict__ out) {
    int j = threadIdx.x;
    if (j < NUM_GRAPHS * NCLS) out[j] = funkey(g_gkey[j]);
}

// ---------------------------------------------------------------------------

extern "C" void kernel_launch(void* const* d_in, const int* in_sizes, int n_in,
                              void* d_out, int out_size) {
    const float* x     = (const float*)d_in[0];
    const int*   ei    = (const int*)d_in[1];
    const int*   batch = (const int*)d_in[2];
    const float* W1    = (const float*)d_in[3];
    const float* b1    = (const float*)d_in[4];
    const float* W2    = (const float*)d_in[5];
    const float* b2    = (const float*)d_in[6];
    float* out = (float*)d_out;

    const int N = in_sizes[2];
    const int F = in_sizes[0] / N;
    const int E = in_sizes[1] / 2;

    const int nbN = (N + 255) / 256;
    const int nbE = (E + 255) / 256;

    zero_kernel<<<nbN, 256>>>(N);
    count_kernel<<<nbE, 256>>>(ei, E);
    scan_kernel<<<nbN, 256>>>(N);
    scatter_kernel<<<nbE, 256>>>(ei, E);

    gemm1_kernel<<<(N + BM - 1) / BM, 256>>>(x, W1, b1, N, F);
    agg1_kernel<<<(4 * N + 255) / 256, 256>>>(N);

    gemm2_kernel<<<nbN, 256>>>(W2, b2, N);
    agg2_kernel<<<(2 * N + 255) / 256, 256>>>(N);

    segmax_logsm_kernel<<<nbN, 256>>>(batch, out, N);
    decode_g_kernel<<<1, 512>>>(out);
}